// round 14
// baseline (speedup 1.0000x reference)
#include <cuda_runtime.h>
#include <cstdint>

// ---------------------------------------------------------------------------
// Persistent 2-layer LSTM, B=512, T=1024, D=4, H=64.
// grid=128 blocks x 256 threads, NB=4 rows/block.
// Thread (kc,u): kc = tid>>6 (k-chunk of 16), u = tid&63 (hidden unit).
// vs round-13 version (1962us): layer-1 weight matrices (W_ih1, W_hh1) are
// REGISTER-CACHED per thread (each thread reads the same 16 quad addresses
// every step -> hoist to 2x16 ulonglong2 reg arrays, loaded once at init).
// Removes 128 of 192 weight LDS wavefronts per warp per step.
// W_hh0 (layer 0) stays in smem to avoid the ~250-reg spill cliff.
// ---------------------------------------------------------------------------

#define NBLK    128
#define NTHR    256
#define NB      4
#define T_STEPS 1024

// smem layout (float offsets)
#define OFF_W0   0            // WT_hh0 quads [64k][64u][4g]
#define OFF_W1   16384        // WT_ih1 (staging for reg preload)
#define OFF_W2   32768        // WT_hh1 (staging for reg preload)
#define OFF_RED  49152        // partials float4 [4kc][4bl][64u] (4096 floats)
#define OFF_H1   53248        // h1 plain f32 [4bl][64u] (256 floats)
#define OFF_H2   53504        // h2 plain f32 (256 floats)
#define OFF_X    53760        // x chunk float4 [4bl][64t] (1024 floats)
#define OFF_HID  54784        // fc1 hidden [4][32]
#define SMEM_FLOATS 54912
#define SMEM_BYTES  (SMEM_FLOATS * 4)   // 219,648 B

__device__ __forceinline__ float sigm_f(float v) {
    float vc = fminf(fmaxf(v, -40.f), 40.f);
    float e  = __expf(-vc);
    return __fdividef(1.f, 1.f + e);
}
__device__ __forceinline__ float tanh_f(float v) {
    float vc = fminf(fmaxf(v, -20.f), 20.f);
    float e  = __expf(-2.f * vc);
    return __fdividef(2.f, 1.f + e) - 1.f;
}

__device__ __forceinline__ void ffma2(unsigned long long& d,
                                      unsigned long long a, unsigned long long b) {
    asm("fma.rn.f32x2 %0, %1, %2, %0;" : "+l"(d) : "l"(a), "l"(b));
}
__device__ __forceinline__ float2 unpack2(unsigned long long v) {
    float2 r;
    asm("mov.b64 {%0, %1}, %2;" : "=f"(r.x), "=f"(r.y) : "l"(v));
    return r;
}
__device__ __forceinline__ unsigned long long pack2(float a, float b) {
    unsigned long long v;
    asm("mov.b64 %0, {%1, %2};" : "=l"(v) : "f"(a), "f"(b));
    return v;
}

// Matvec partials with SMEM-resident weights (layer 0).
__device__ __forceinline__ void mv_part_smem(unsigned long long aif[NB],
                                             unsigned long long ago[NB],
                                             const ulonglong2* __restrict__ Wq,
                                             const float* __restrict__ hf,
                                             int kc, int u) {
#pragma unroll
    for (int j = 0; j < 16; j += 4) {
        int k = kc * 16 + j;
        ulonglong2 w0 = Wq[(k + 0) * 64 + u];
        ulonglong2 w1 = Wq[(k + 1) * 64 + u];
        ulonglong2 w2 = Wq[(k + 2) * 64 + u];
        ulonglong2 w3 = Wq[(k + 3) * 64 + u];
#pragma unroll
        for (int bl = 0; bl < NB; bl++) {
            float4 hv = *(const float4*)&hf[bl * 64 + k];   // 1 broadcast LDS.128
            unsigned long long h0 = pack2(hv.x, hv.x);
            unsigned long long h1 = pack2(hv.y, hv.y);
            unsigned long long h2 = pack2(hv.z, hv.z);
            unsigned long long h3 = pack2(hv.w, hv.w);
            ffma2(aif[bl], w0.x, h0);
            ffma2(ago[bl], w0.y, h0);
            ffma2(aif[bl], w1.x, h1);
            ffma2(ago[bl], w1.y, h1);
            ffma2(aif[bl], w2.x, h2);
            ffma2(ago[bl], w2.y, h2);
            ffma2(aif[bl], w3.x, h3);
            ffma2(ago[bl], w3.y, h3);
        }
    }
}

// Matvec partials with REGISTER-resident weights (layer 1). wr indexed by
// compile-time j only so the array stays in registers.
__device__ __forceinline__ void mv_part_reg(unsigned long long aif[NB],
                                            unsigned long long ago[NB],
                                            const ulonglong2 (&wr)[16],
                                            const float* __restrict__ hf,
                                            int kc) {
#pragma unroll
    for (int j = 0; j < 16; j += 4) {
        int k = kc * 16 + j;
#pragma unroll
        for (int bl = 0; bl < NB; bl++) {
            float4 hv = *(const float4*)&hf[bl * 64 + k];   // 1 broadcast LDS.128
            unsigned long long h0 = pack2(hv.x, hv.x);
            unsigned long long h1 = pack2(hv.y, hv.y);
            unsigned long long h2 = pack2(hv.z, hv.z);
            unsigned long long h3 = pack2(hv.w, hv.w);
            ffma2(aif[bl], wr[j + 0].x, h0);
            ffma2(ago[bl], wr[j + 0].y, h0);
            ffma2(aif[bl], wr[j + 1].x, h1);
            ffma2(ago[bl], wr[j + 1].y, h1);
            ffma2(aif[bl], wr[j + 2].x, h2);
            ffma2(ago[bl], wr[j + 2].y, h2);
            ffma2(aif[bl], wr[j + 3].x, h3);
            ffma2(ago[bl], wr[j + 3].y, h3);
        }
    }
}

__device__ __forceinline__ float final_gate(float4 pre, float& c) {
    float gi = sigm_f(pre.x);
    float gf = sigm_f(pre.y);
    float gg = tanh_f(pre.z);
    float go = sigm_f(pre.w);
    c = fmaf(gf, c, gi * gg);
    return go * tanh_f(c);
}

__global__ void __launch_bounds__(NTHR, 1)
lstm_persistent_kernel(const float* __restrict__ x,
                       const float* __restrict__ Wih0, const float* __restrict__ Whh0,
                       const float* __restrict__ b0,
                       const float* __restrict__ Wih1, const float* __restrict__ Whh1,
                       const float* __restrict__ b1,
                       const float* __restrict__ Wfc1, const float* __restrict__ bfc1,
                       const float* __restrict__ Wfc2, const float* __restrict__ bfc2,
                       float* __restrict__ out) {
    extern __shared__ float sm[];
    float*  sW0  = sm + OFF_W0;
    float*  sW1  = sm + OFF_W1;
    float*  sW2  = sm + OFF_W2;
    float4* red4 = (float4*)(sm + OFF_RED);
    float*  h1f  = sm + OFF_H1;
    float*  h2f  = sm + OFF_H2;
    float4* sx4  = (float4*)(sm + OFF_X);
    float*  shid = sm + OFF_HID;

    const int tid = threadIdx.x;
    const int kc  = tid >> 6;   // k-chunk 0..3 (also the batch row this thread finalizes)
    const int u   = tid & 63;   // hidden unit 0..63

    // ---- transpose-load recurrent weights into quad layout ---------------
    // global W[row][k] (256x64), row = gt*64 + unit  ->  smem[(k*64+unit)*4 + gt]
    for (int idx = tid; idx < 256 * 64; idx += NTHR) {
        int row = idx >> 6, k = idx & 63;
        int un = row & 63, gt = row >> 6;
        int dst = (k * 64 + un) * 4 + gt;
        sW0[dst] = Whh0[idx];
        sW1[dst] = Wih1[idx];
        sW2[dst] = Whh1[idx];
    }

    // ---- per-thread register data ----------------------------------------
    float4 wx[4];
#pragma unroll
    for (int d = 0; d < 4; d++)
        wx[d] = make_float4(Wih0[u * 4 + d], Wih0[(64 + u) * 4 + d],
                            Wih0[(128 + u) * 4 + d], Wih0[(192 + u) * 4 + d]);
    float4 b0q = make_float4(b0[u], b0[64 + u], b0[128 + u], b0[192 + u]);
    float4 b1q = make_float4(b1[u], b1[64 + u], b1[128 + u], b1[192 + u]);

    // ---- init state -------------------------------------------------------
    h1f[tid] = 0.f;   // tid spans exactly 4*64 entries
    h2f[tid] = 0.f;
    float c1 = 0.f, c2 = 0.f;
    __syncthreads();

    const ulonglong2* W0q = (const ulonglong2*)sW0;
    const ulonglong2* W1q = (const ulonglong2*)sW1;
    const ulonglong2* W2q = (const ulonglong2*)sW2;

    // ---- register-cache layer-1 weights (fixed addresses for this thread)
    ulonglong2 w1r[16], w2r[16];
#pragma unroll
    for (int j = 0; j < 16; j++) {
        w1r[j] = W1q[(kc * 16 + j) * 64 + u];
        w2r[j] = W2q[(kc * 16 + j) * 64 + u];
    }

    const float4* x4 = (const float4*)x;   // one float4 per (b, t)
    const size_t xbase = (size_t)(blockIdx.x * NB + kc) * T_STEPS;  // kc doubles as bl for staging

    for (int t = 0; t < T_STEPS; t++) {
        const int tl = t & 63;
        if (tl == 0) {
            // stage next 64 timesteps of x for our 4 batch rows (coalesced);
            // read of this chunk happens only after barrier #1 below.
            sx4[kc * 64 + u] = x4[xbase + t + u];
        }

        // ---- layer 0 partials + store ------------------------------------
        {
            unsigned long long aif[NB] = {0ull, 0ull, 0ull, 0ull};
            unsigned long long ago[NB] = {0ull, 0ull, 0ull, 0ull};
            mv_part_smem(aif, ago, W0q, h1f, kc, u);
#pragma unroll
            for (int bl = 0; bl < NB; bl++) {
                float2 fi = unpack2(aif[bl]);
                float2 fo = unpack2(ago[bl]);
                red4[(kc * 4 + bl) * 64 + u] = make_float4(fi.x, fi.y, fo.x, fo.y);
            }
        }
        __syncthreads();   // #1: red4 stores + sx4 staging -> finalize reads

        // ---- layer 0 finalize (this thread owns bl = kc) -----------------
        {
            float4 pre = b0q;
#pragma unroll
            for (int kk = 0; kk < 4; kk++) {
                float4 q = red4[(kk * 4 + kc) * 64 + u];
                pre.x += q.x; pre.y += q.y; pre.z += q.z; pre.w += q.w;
            }
            float4 xv = sx4[kc * 64 + tl];
            pre.x = fmaf(wx[0].x, xv.x, fmaf(wx[1].x, xv.y, fmaf(wx[2].x, xv.z, fmaf(wx[3].x, xv.w, pre.x))));
            pre.y = fmaf(wx[0].y, xv.x, fmaf(wx[1].y, xv.y, fmaf(wx[2].y, xv.z, fmaf(wx[3].y, xv.w, pre.y))));
            pre.z = fmaf(wx[0].z, xv.x, fmaf(wx[1].z, xv.y, fmaf(wx[2].z, xv.z, fmaf(wx[3].z, xv.w, pre.z))));
            pre.w = fmaf(wx[0].w, xv.x, fmaf(wx[1].w, xv.y, fmaf(wx[2].w, xv.z, fmaf(wx[3].w, xv.w, pre.w))));
            float h = final_gate(pre, c1);
            h1f[kc * 64 + u] = h;
        }
        __syncthreads();   // #2: h1 publish + red4 read -> layer-1 partials

        // ---- layer 1 partials + store (register weights) -----------------
        {
            unsigned long long aif[NB] = {0ull, 0ull, 0ull, 0ull};
            unsigned long long ago[NB] = {0ull, 0ull, 0ull, 0ull};
            mv_part_reg(aif, ago, w1r, h1f, kc);
            mv_part_reg(aif, ago, w2r, h2f, kc);
#pragma unroll
            for (int bl = 0; bl < NB; bl++) {
                float2 fi = unpack2(aif[bl]);
                float2 fo = unpack2(ago[bl]);
                red4[(kc * 4 + bl) * 64 + u] = make_float4(fi.x, fi.y, fo.x, fo.y);
            }
        }
        __syncthreads();   // #3: red4 stores -> finalize reads

        // ---- layer 1 finalize --------------------------------------------
        {
            float4 pre = b1q;
#pragma unroll
            for (int kk = 0; kk < 4; kk++) {
                float4 q = red4[(kk * 4 + kc) * 64 + u];
                pre.x += q.x; pre.y += q.y; pre.z += q.z; pre.w += q.w;
            }
            float h = final_gate(pre, c2);
            h2f[kc * 64 + u] = h;
        }
        __syncthreads();   // #4: red4 read + h2 publish -> next step's writes
    }

    // ---- classifier head: Linear(64,32) -> ReLU -> Linear(32,1) -> sigmoid
    if (tid < 128) {
        int cb = tid >> 5, m = tid & 31;
        float s = bfc1[m];
        const float* wr = Wfc1 + m * 64;
#pragma unroll
        for (int k = 0; k < 64; k++) s = fmaf(wr[k], h2f[cb * 64 + k], s);
        shid[cb * 32 + m] = fmaxf(s, 0.f);
    }
    __syncthreads();
    if (tid < NB) {
        float s = bfc2[0];
#pragma unroll
        for (int m = 0; m < 32; m++) s = fmaf(Wfc2[m], shid[tid * 32 + m], s);
        out[blockIdx.x * NB + tid] = sigm_f(s);
    }
}

extern "C" void kernel_launch(void* const* d_in, const int* in_sizes, int n_in,
                              void* d_out, int out_size) {
    const float* x    = (const float*)d_in[0];
    const float* Wih0 = (const float*)d_in[1];
    const float* Whh0 = (const float*)d_in[2];
    const float* b0   = (const float*)d_in[3];
    const float* Wih1 = (const float*)d_in[4];
    const float* Whh1 = (const float*)d_in[5];
    const float* b1   = (const float*)d_in[6];
    const float* Wfc1 = (const float*)d_in[7];
    const float* bfc1 = (const float*)d_in[8];
    const float* Wfc2 = (const float*)d_in[9];
    const float* bfc2 = (const float*)d_in[10];
    float* out = (float*)d_out;

    cudaFuncSetAttribute(lstm_persistent_kernel,
                         cudaFuncAttributeMaxDynamicSharedMemorySize, SMEM_BYTES);
    lstm_persistent_kernel<<<NBLK, NTHR, SMEM_BYTES>>>(
        x, Wih0, Whh0, b0, Wih1, Whh1, b1, Wfc1, bfc1, Wfc2, bfc2, out);
}

// round 16
// speedup vs baseline: 1.5500x; 1.5500x over previous
#include <cuda_runtime.h>
#include <cstdint>

// ---------------------------------------------------------------------------
// Persistent 2-layer LSTM, B=512, T=1024, D=4, H=64.
// grid=128 blocks x 256 threads, NB=4 rows/block.
// Thread (kc,u): kc = tid>>6 (k-chunk of 16), u = tid&63 (hidden unit).
// vs round-13 best (1962us): ONLY W_hh1 is register-cached (16 ulonglong2 =
// 32 regs/thread). Round-14 showed caching two matrices (241 regs) spills to
// local and regresses; one matrix stays under the cliff and removes 64 of
// 307 LDS wavefronts per warp per step.
// ---------------------------------------------------------------------------

#define NBLK    128
#define NTHR    256
#define NB      4
#define T_STEPS 1024

// smem layout (float offsets)
#define OFF_W0   0            // WT_hh0 quads [64k][64u][4g]
#define OFF_W1   16384        // WT_ih1
#define OFF_W2   32768        // WT_hh1 (staging for reg preload only)
#define OFF_RED  49152        // partials float4 [4kc][4bl][64u] (4096 floats)
#define OFF_H1   53248        // h1 plain f32 [4bl][64u] (256 floats)
#define OFF_H2   53504        // h2 plain f32 (256 floats)
#define OFF_X    53760        // x chunk float4 [4bl][64t] (1024 floats)
#define OFF_HID  54784        // fc1 hidden [4][32]
#define SMEM_FLOATS 54912
#define SMEM_BYTES  (SMEM_FLOATS * 4)   // 219,648 B

__device__ __forceinline__ float sigm_f(float v) {
    float vc = fminf(fmaxf(v, -40.f), 40.f);
    float e  = __expf(-vc);
    return __fdividef(1.f, 1.f + e);
}
__device__ __forceinline__ float tanh_f(float v) {
    float vc = fminf(fmaxf(v, -20.f), 20.f);
    float e  = __expf(-2.f * vc);
    return __fdividef(2.f, 1.f + e) - 1.f;
}

__device__ __forceinline__ void ffma2(unsigned long long& d,
                                      unsigned long long a, unsigned long long b) {
    asm("fma.rn.f32x2 %0, %1, %2, %0;" : "+l"(d) : "l"(a), "l"(b));
}
__device__ __forceinline__ float2 unpack2(unsigned long long v) {
    float2 r;
    asm("mov.b64 {%0, %1}, %2;" : "=f"(r.x), "=f"(r.y) : "l"(v));
    return r;
}
__device__ __forceinline__ unsigned long long pack2(float a, float b) {
    unsigned long long v;
    asm("mov.b64 %0, {%1, %2};" : "=l"(v) : "f"(a), "f"(b));
    return v;
}

// Matvec partials with SMEM-resident weights.
__device__ __forceinline__ void mv_part_smem(unsigned long long aif[NB],
                                             unsigned long long ago[NB],
                                             const ulonglong2* __restrict__ Wq,
                                             const float* __restrict__ hf,
                                             int kc, int u) {
#pragma unroll
    for (int j = 0; j < 16; j += 4) {
        int k = kc * 16 + j;
        ulonglong2 w0 = Wq[(k + 0) * 64 + u];
        ulonglong2 w1 = Wq[(k + 1) * 64 + u];
        ulonglong2 w2 = Wq[(k + 2) * 64 + u];
        ulonglong2 w3 = Wq[(k + 3) * 64 + u];
#pragma unroll
        for (int bl = 0; bl < NB; bl++) {
            float4 hv = *(const float4*)&hf[bl * 64 + k];   // 1 broadcast LDS.128
            unsigned long long h0 = pack2(hv.x, hv.x);
            unsigned long long h1 = pack2(hv.y, hv.y);
            unsigned long long h2 = pack2(hv.z, hv.z);
            unsigned long long h3 = pack2(hv.w, hv.w);
            ffma2(aif[bl], w0.x, h0);
            ffma2(ago[bl], w0.y, h0);
            ffma2(aif[bl], w1.x, h1);
            ffma2(ago[bl], w1.y, h1);
            ffma2(aif[bl], w2.x, h2);
            ffma2(ago[bl], w2.y, h2);
            ffma2(aif[bl], w3.x, h3);
            ffma2(ago[bl], w3.y, h3);
        }
    }
}

// Matvec partials with REGISTER-resident weights (W_hh1 only). wr indexed by
// compile-time j so the array stays in registers.
__device__ __forceinline__ void mv_part_reg(unsigned long long aif[NB],
                                            unsigned long long ago[NB],
                                            const ulonglong2 (&wr)[16],
                                            const float* __restrict__ hf,
                                            int kc) {
#pragma unroll
    for (int j = 0; j < 16; j += 4) {
        int k = kc * 16 + j;
#pragma unroll
        for (int bl = 0; bl < NB; bl++) {
            float4 hv = *(const float4*)&hf[bl * 64 + k];   // 1 broadcast LDS.128
            unsigned long long h0 = pack2(hv.x, hv.x);
            unsigned long long h1 = pack2(hv.y, hv.y);
            unsigned long long h2 = pack2(hv.z, hv.z);
            unsigned long long h3 = pack2(hv.w, hv.w);
            ffma2(aif[bl], wr[j + 0].x, h0);
            ffma2(ago[bl], wr[j + 0].y, h0);
            ffma2(aif[bl], wr[j + 1].x, h1);
            ffma2(ago[bl], wr[j + 1].y, h1);
            ffma2(aif[bl], wr[j + 2].x, h2);
            ffma2(ago[bl], wr[j + 2].y, h2);
            ffma2(aif[bl], wr[j + 3].x, h3);
            ffma2(ago[bl], wr[j + 3].y, h3);
        }
    }
}

__device__ __forceinline__ float final_gate(float4 pre, float& c) {
    float gi = sigm_f(pre.x);
    float gf = sigm_f(pre.y);
    float gg = tanh_f(pre.z);
    float go = sigm_f(pre.w);
    c = fmaf(gf, c, gi * gg);
    return go * tanh_f(c);
}

__global__ void __launch_bounds__(NTHR, 1)
lstm_persistent_kernel(const float* __restrict__ x,
                       const float* __restrict__ Wih0, const float* __restrict__ Whh0,
                       const float* __restrict__ b0,
                       const float* __restrict__ Wih1, const float* __restrict__ Whh1,
                       const float* __restrict__ b1,
                       const float* __restrict__ Wfc1, const float* __restrict__ bfc1,
                       const float* __restrict__ Wfc2, const float* __restrict__ bfc2,
                       float* __restrict__ out) {
    extern __shared__ float sm[];
    float*  sW0  = sm + OFF_W0;
    float*  sW1  = sm + OFF_W1;
    float*  sW2  = sm + OFF_W2;
    float4* red4 = (float4*)(sm + OFF_RED);
    float*  h1f  = sm + OFF_H1;
    float*  h2f  = sm + OFF_H2;
    float4* sx4  = (float4*)(sm + OFF_X);
    float*  shid = sm + OFF_HID;

    const int tid = threadIdx.x;
    const int kc  = tid >> 6;   // k-chunk 0..3 (also the batch row this thread finalizes)
    const int u   = tid & 63;   // hidden unit 0..63

    // ---- transpose-load recurrent weights into quad layout ---------------
    // global W[row][k] (256x64), row = gt*64 + unit  ->  smem[(k*64+unit)*4 + gt]
    for (int idx = tid; idx < 256 * 64; idx += NTHR) {
        int row = idx >> 6, k = idx & 63;
        int un = row & 63, gt = row >> 6;
        int dst = (k * 64 + un) * 4 + gt;
        sW0[dst] = Whh0[idx];
        sW1[dst] = Wih1[idx];
        sW2[dst] = Whh1[idx];
    }

    // ---- per-thread register data ----------------------------------------
    float4 wx[4];
#pragma unroll
    for (int d = 0; d < 4; d++)
        wx[d] = make_float4(Wih0[u * 4 + d], Wih0[(64 + u) * 4 + d],
                            Wih0[(128 + u) * 4 + d], Wih0[(192 + u) * 4 + d]);
    float4 b0q = make_float4(b0[u], b0[64 + u], b0[128 + u], b0[192 + u]);
    float4 b1q = make_float4(b1[u], b1[64 + u], b1[128 + u], b1[192 + u]);

    // ---- init state -------------------------------------------------------
    h1f[tid] = 0.f;   // tid spans exactly 4*64 entries
    h2f[tid] = 0.f;
    float c1 = 0.f, c2 = 0.f;
    __syncthreads();

    const ulonglong2* W0q = (const ulonglong2*)sW0;
    const ulonglong2* W1q = (const ulonglong2*)sW1;
    const ulonglong2* W2q = (const ulonglong2*)sW2;

    // ---- register-cache W_hh1 only (32 regs; fixed addresses per thread)
    ulonglong2 w2r[16];
#pragma unroll
    for (int j = 0; j < 16; j++)
        w2r[j] = W2q[(kc * 16 + j) * 64 + u];

    const float4* x4 = (const float4*)x;   // one float4 per (b, t)
    const size_t xbase = (size_t)(blockIdx.x * NB + kc) * T_STEPS;  // kc doubles as bl for staging

    for (int t = 0; t < T_STEPS; t++) {
        const int tl = t & 63;
        if (tl == 0) {
            // stage next 64 timesteps of x for our 4 batch rows (coalesced);
            // read of this chunk happens only after barrier #1 below.
            sx4[kc * 64 + u] = x4[xbase + t + u];
        }

        // ---- layer 0 partials + store ------------------------------------
        {
            unsigned long long aif[NB] = {0ull, 0ull, 0ull, 0ull};
            unsigned long long ago[NB] = {0ull, 0ull, 0ull, 0ull};
            mv_part_smem(aif, ago, W0q, h1f, kc, u);
#pragma unroll
            for (int bl = 0; bl < NB; bl++) {
                float2 fi = unpack2(aif[bl]);
                float2 fo = unpack2(ago[bl]);
                red4[(kc * 4 + bl) * 64 + u] = make_float4(fi.x, fi.y, fo.x, fo.y);
            }
        }
        __syncthreads();   // #1: red4 stores + sx4 staging -> finalize reads

        // ---- layer 0 finalize (this thread owns bl = kc) -----------------
        {
            float4 pre = b0q;
#pragma unroll
            for (int kk = 0; kk < 4; kk++) {
                float4 q = red4[(kk * 4 + kc) * 64 + u];
                pre.x += q.x; pre.y += q.y; pre.z += q.z; pre.w += q.w;
            }
            float4 xv = sx4[kc * 64 + tl];
            pre.x = fmaf(wx[0].x, xv.x, fmaf(wx[1].x, xv.y, fmaf(wx[2].x, xv.z, fmaf(wx[3].x, xv.w, pre.x))));
            pre.y = fmaf(wx[0].y, xv.x, fmaf(wx[1].y, xv.y, fmaf(wx[2].y, xv.z, fmaf(wx[3].y, xv.w, pre.y))));
            pre.z = fmaf(wx[0].z, xv.x, fmaf(wx[1].z, xv.y, fmaf(wx[2].z, xv.z, fmaf(wx[3].z, xv.w, pre.z))));
            pre.w = fmaf(wx[0].w, xv.x, fmaf(wx[1].w, xv.y, fmaf(wx[2].w, xv.z, fmaf(wx[3].w, xv.w, pre.w))));
            float h = final_gate(pre, c1);
            h1f[kc * 64 + u] = h;
        }
        __syncthreads();   // #2: h1 publish + red4 read -> layer-1 partials

        // ---- layer 1 partials + store ------------------------------------
        {
            unsigned long long aif[NB] = {0ull, 0ull, 0ull, 0ull};
            unsigned long long ago[NB] = {0ull, 0ull, 0ull, 0ull};
            mv_part_smem(aif, ago, W1q, h1f, kc, u);   // W_ih1 from smem
            mv_part_reg(aif, ago, w2r, h2f, kc);       // W_hh1 from registers
#pragma unroll
            for (int bl = 0; bl < NB; bl++) {
                float2 fi = unpack2(aif[bl]);
                float2 fo = unpack2(ago[bl]);
                red4[(kc * 4 + bl) * 64 + u] = make_float4(fi.x, fi.y, fo.x, fo.y);
            }
        }
        __syncthreads();   // #3: red4 stores -> finalize reads

        // ---- layer 1 finalize --------------------------------------------
        {
            float4 pre = b1q;
#pragma unroll
            for (int kk = 0; kk < 4; kk++) {
                float4 q = red4[(kk * 4 + kc) * 64 + u];
                pre.x += q.x; pre.y += q.y; pre.z += q.z; pre.w += q.w;
            }
            float h = final_gate(pre, c2);
            h2f[kc * 64 + u] = h;
        }
        __syncthreads();   // #4: red4 read + h2 publish -> next step's writes
    }

    // ---- classifier head: Linear(64,32) -> ReLU -> Linear(32,1) -> sigmoid
    if (tid < 128) {
        int cb = tid >> 5, m = tid & 31;
        float s = bfc1[m];
        const float* wr = Wfc1 + m * 64;
#pragma unroll
        for (int k = 0; k < 64; k++) s = fmaf(wr[k], h2f[cb * 64 + k], s);
        shid[cb * 32 + m] = fmaxf(s, 0.f);
    }
    __syncthreads();
    if (tid < NB) {
        float s = bfc2[0];
#pragma unroll
        for (int m = 0; m < 32; m++) s = fmaf(Wfc2[m], shid[tid * 32 + m], s);
        out[blockIdx.x * NB + tid] = sigm_f(s);
    }
}

extern "C" void kernel_launch(void* const* d_in, const int* in_sizes, int n_in,
                              void* d_out, int out_size) {
    const float* x    = (const float*)d_in[0];
    const float* Wih0 = (const float*)d_in[1];
    const float* Whh0 = (const float*)d_in[2];
    const float* b0   = (const float*)d_in[3];
    const float* Wih1 = (const float*)d_in[4];
    const float* Whh1 = (const float*)d_in[5];
    const float* b1   = (const float*)d_in[6];
    const float* Wfc1 = (const float*)d_in[7];
    const float* bfc1 = (const float*)d_in[8];
    const float* Wfc2 = (const float*)d_in[9];
    const float* bfc2 = (const float*)d_in[10];
    float* out = (float*)d_out;

    cudaFuncSetAttribute(lstm_persistent_kernel,
                         cudaFuncAttributeMaxDynamicSharedMemorySize, SMEM_BYTES);
    lstm_persistent_kernel<<<NBLK, NTHR, SMEM_BYTES>>>(
        x, Wih0, Whh0, b0, Wih1, Whh1, b1, Wfc1, bfc1, Wfc2, bfc2, out);
}

// round 17
// speedup vs baseline: 1.5576x; 1.0049x over previous
#include <cuda_runtime.h>
#include <cstdint>

// ---------------------------------------------------------------------------
// Persistent 2-layer LSTM, B=512, T=1024, D=4, H=64.
// grid=128 blocks x 256 threads, NB=4 rows/block.
// Thread (kc,u): kc = tid>>6 (k-chunk of 16), u = tid&63 (hidden unit).
// vs round-16 best (1815us): layer-0 and layer-1 use SEPARATE reduction
// buffers (redA / redB; redB reuses the W_hh1 smem staging area freed by the
// register cache) -> barrier #4 is removed and the loop back-edge is
// barrier-free, letting warps skew across the step boundary.
// Race audit: h1 W#2/R(#1-next), h2 W#3/R(C after #1,#2), redA W->#1->R,
// redB W->#3->R, sx4 W->#1->R; every pair crosses a barrier.
// ---------------------------------------------------------------------------

#define NBLK    128
#define NTHR    256
#define NB      4
#define T_STEPS 1024

// smem layout (float offsets)
#define OFF_W0   0            // WT_hh0 quads [64k][64u][4g]
#define OFF_W1   16384        // WT_ih1
#define OFF_W2   32768        // WT_hh1 staging (init only) -> redB after init
#define OFF_REDB 32768        // layer-1 partials float4 (4096 floats, aliases W2)
#define OFF_REDA 49152        // layer-0 partials float4 [4kc][4bl][64u]
#define OFF_H1   53248        // h1 plain f32 [4bl][64u] (256 floats)
#define OFF_H2   53504        // h2 plain f32 (256 floats)
#define OFF_X    53760        // x chunk float4 [4bl][64t] (1024 floats)
#define OFF_HID  54784        // fc1 hidden [4][32]
#define SMEM_FLOATS 54912
#define SMEM_BYTES  (SMEM_FLOATS * 4)   // 219,648 B

__device__ __forceinline__ float sigm_f(float v) {
    float vc = fminf(fmaxf(v, -40.f), 40.f);
    float e  = __expf(-vc);
    return __fdividef(1.f, 1.f + e);
}
__device__ __forceinline__ float tanh_f(float v) {
    float vc = fminf(fmaxf(v, -20.f), 20.f);
    float e  = __expf(-2.f * vc);
    return __fdividef(2.f, 1.f + e) - 1.f;
}

__device__ __forceinline__ void ffma2(unsigned long long& d,
                                      unsigned long long a, unsigned long long b) {
    asm("fma.rn.f32x2 %0, %1, %2, %0;" : "+l"(d) : "l"(a), "l"(b));
}
__device__ __forceinline__ float2 unpack2(unsigned long long v) {
    float2 r;
    asm("mov.b64 {%0, %1}, %2;" : "=f"(r.x), "=f"(r.y) : "l"(v));
    return r;
}
__device__ __forceinline__ unsigned long long pack2(float a, float b) {
    unsigned long long v;
    asm("mov.b64 %0, {%1, %2};" : "=l"(v) : "f"(a), "f"(b));
    return v;
}

// Matvec partials with SMEM-resident weights.
__device__ __forceinline__ void mv_part_smem(unsigned long long aif[NB],
                                             unsigned long long ago[NB],
                                             const ulonglong2* __restrict__ Wq,
                                             const float* __restrict__ hf,
                                             int kc, int u) {
#pragma unroll
    for (int j = 0; j < 16; j += 4) {
        int k = kc * 16 + j;
        ulonglong2 w0 = Wq[(k + 0) * 64 + u];
        ulonglong2 w1 = Wq[(k + 1) * 64 + u];
        ulonglong2 w2 = Wq[(k + 2) * 64 + u];
        ulonglong2 w3 = Wq[(k + 3) * 64 + u];
#pragma unroll
        for (int bl = 0; bl < NB; bl++) {
            float4 hv = *(const float4*)&hf[bl * 64 + k];   // 1 broadcast LDS.128
            unsigned long long h0 = pack2(hv.x, hv.x);
            unsigned long long h1 = pack2(hv.y, hv.y);
            unsigned long long h2 = pack2(hv.z, hv.z);
            unsigned long long h3 = pack2(hv.w, hv.w);
            ffma2(aif[bl], w0.x, h0);
            ffma2(ago[bl], w0.y, h0);
            ffma2(aif[bl], w1.x, h1);
            ffma2(ago[bl], w1.y, h1);
            ffma2(aif[bl], w2.x, h2);
            ffma2(ago[bl], w2.y, h2);
            ffma2(aif[bl], w3.x, h3);
            ffma2(ago[bl], w3.y, h3);
        }
    }
}

// Matvec partials with REGISTER-resident weights (W_hh1). wr indexed by
// compile-time j so the array stays in registers.
__device__ __forceinline__ void mv_part_reg(unsigned long long aif[NB],
                                            unsigned long long ago[NB],
                                            const ulonglong2 (&wr)[16],
                                            const float* __restrict__ hf,
                                            int kc) {
#pragma unroll
    for (int j = 0; j < 16; j += 4) {
        int k = kc * 16 + j;
#pragma unroll
        for (int bl = 0; bl < NB; bl++) {
            float4 hv = *(const float4*)&hf[bl * 64 + k];   // 1 broadcast LDS.128
            unsigned long long h0 = pack2(hv.x, hv.x);
            unsigned long long h1 = pack2(hv.y, hv.y);
            unsigned long long h2 = pack2(hv.z, hv.z);
            unsigned long long h3 = pack2(hv.w, hv.w);
            ffma2(aif[bl], wr[j + 0].x, h0);
            ffma2(ago[bl], wr[j + 0].y, h0);
            ffma2(aif[bl], wr[j + 1].x, h1);
            ffma2(ago[bl], wr[j + 1].y, h1);
            ffma2(aif[bl], wr[j + 2].x, h2);
            ffma2(ago[bl], wr[j + 2].y, h2);
            ffma2(aif[bl], wr[j + 3].x, h3);
            ffma2(ago[bl], wr[j + 3].y, h3);
        }
    }
}

__device__ __forceinline__ float final_gate(float4 pre, float& c) {
    float gi = sigm_f(pre.x);
    float gf = sigm_f(pre.y);
    float gg = tanh_f(pre.z);
    float go = sigm_f(pre.w);
    c = fmaf(gf, c, gi * gg);
    return go * tanh_f(c);
}

__global__ void __launch_bounds__(NTHR, 1)
lstm_persistent_kernel(const float* __restrict__ x,
                       const float* __restrict__ Wih0, const float* __restrict__ Whh0,
                       const float* __restrict__ b0,
                       const float* __restrict__ Wih1, const float* __restrict__ Whh1,
                       const float* __restrict__ b1,
                       const float* __restrict__ Wfc1, const float* __restrict__ bfc1,
                       const float* __restrict__ Wfc2, const float* __restrict__ bfc2,
                       float* __restrict__ out) {
    extern __shared__ float sm[];
    float*  sW0   = sm + OFF_W0;
    float*  sW1   = sm + OFF_W1;
    float*  sW2   = sm + OFF_W2;     // staging only; aliased by redB after init
    float4* redA4 = (float4*)(sm + OFF_REDA);
    float4* redB4 = (float4*)(sm + OFF_REDB);
    float*  h1f   = sm + OFF_H1;
    float*  h2f   = sm + OFF_H2;
    float4* sx4   = (float4*)(sm + OFF_X);
    float*  shid  = sm + OFF_HID;

    const int tid = threadIdx.x;
    const int kc  = tid >> 6;   // k-chunk 0..3 (also the batch row this thread finalizes)
    const int u   = tid & 63;   // hidden unit 0..63

    // ---- transpose-load recurrent weights into quad layout ---------------
    // global W[row][k] (256x64), row = gt*64 + unit  ->  smem[(k*64+unit)*4 + gt]
    for (int idx = tid; idx < 256 * 64; idx += NTHR) {
        int row = idx >> 6, k = idx & 63;
        int un = row & 63, gt = row >> 6;
        int dst = (k * 64 + un) * 4 + gt;
        sW0[dst] = Whh0[idx];
        sW1[dst] = Wih1[idx];
        sW2[dst] = Whh1[idx];
    }

    // ---- per-thread register data ----------------------------------------
    float4 wx[4];
#pragma unroll
    for (int d = 0; d < 4; d++)
        wx[d] = make_float4(Wih0[u * 4 + d], Wih0[(64 + u) * 4 + d],
                            Wih0[(128 + u) * 4 + d], Wih0[(192 + u) * 4 + d]);
    float4 b0q = make_float4(b0[u], b0[64 + u], b0[128 + u], b0[192 + u]);
    float4 b1q = make_float4(b1[u], b1[64 + u], b1[128 + u], b1[192 + u]);

    // ---- init state -------------------------------------------------------
    h1f[tid] = 0.f;   // tid spans exactly 4*64 entries
    h2f[tid] = 0.f;
    float c1 = 0.f, c2 = 0.f;
    __syncthreads();

    const ulonglong2* W0q = (const ulonglong2*)sW0;
    const ulonglong2* W1q = (const ulonglong2*)sW1;
    const ulonglong2* W2q = (const ulonglong2*)sW2;

    // ---- register-cache W_hh1 (32 regs; fixed addresses per thread) ------
    ulonglong2 w2r[16];
#pragma unroll
    for (int j = 0; j < 16; j++)
        w2r[j] = W2q[(kc * 16 + j) * 64 + u];
    __syncthreads();   // all threads done reading W2 staging before redB aliases it

    const float4* x4 = (const float4*)x;   // one float4 per (b, t)
    const size_t xbase = (size_t)(blockIdx.x * NB + kc) * T_STEPS;  // kc doubles as bl for staging

    for (int t = 0; t < T_STEPS; t++) {
        const int tl = t & 63;
        if (tl == 0) {
            // stage next 64 timesteps of x for our 4 batch rows (coalesced);
            // read of this chunk happens only after barrier #1 below.
            sx4[kc * 64 + u] = x4[xbase + t + u];
        }

        // ---- A: layer 0 partials -> redA ---------------------------------
        {
            unsigned long long aif[NB] = {0ull, 0ull, 0ull, 0ull};
            unsigned long long ago[NB] = {0ull, 0ull, 0ull, 0ull};
            mv_part_smem(aif, ago, W0q, h1f, kc, u);
#pragma unroll
            for (int bl = 0; bl < NB; bl++) {
                float2 fi = unpack2(aif[bl]);
                float2 fo = unpack2(ago[bl]);
                redA4[(kc * 4 + bl) * 64 + u] = make_float4(fi.x, fi.y, fo.x, fo.y);
            }
        }
        __syncthreads();   // #1: redA stores + sx4 staging -> B reads

        // ---- B: layer 0 finalize (this thread owns bl = kc) --------------
        {
            float4 pre = b0q;
#pragma unroll
            for (int kk = 0; kk < 4; kk++) {
                float4 q = redA4[(kk * 4 + kc) * 64 + u];
                pre.x += q.x; pre.y += q.y; pre.z += q.z; pre.w += q.w;
            }
            float4 xv = sx4[kc * 64 + tl];
            pre.x = fmaf(wx[0].x, xv.x, fmaf(wx[1].x, xv.y, fmaf(wx[2].x, xv.z, fmaf(wx[3].x, xv.w, pre.x))));
            pre.y = fmaf(wx[0].y, xv.x, fmaf(wx[1].y, xv.y, fmaf(wx[2].y, xv.z, fmaf(wx[3].y, xv.w, pre.y))));
            pre.z = fmaf(wx[0].z, xv.x, fmaf(wx[1].z, xv.y, fmaf(wx[2].z, xv.z, fmaf(wx[3].z, xv.w, pre.z))));
            pre.w = fmaf(wx[0].w, xv.x, fmaf(wx[1].w, xv.y, fmaf(wx[2].w, xv.z, fmaf(wx[3].w, xv.w, pre.w))));
            float h = final_gate(pre, c1);
            h1f[kc * 64 + u] = h;
        }
        __syncthreads();   // #2: h1 publish + redA read -> C

        // ---- C: layer 1 partials -> redB ---------------------------------
        {
            unsigned long long aif[NB] = {0ull, 0ull, 0ull, 0ull};
            unsigned long long ago[NB] = {0ull, 0ull, 0ull, 0ull};
            mv_part_smem(aif, ago, W1q, h1f, kc, u);   // W_ih1 from smem
            mv_part_reg(aif, ago, w2r, h2f, kc);       // W_hh1 from registers
#pragma unroll
            for (int bl = 0; bl < NB; bl++) {
                float2 fi = unpack2(aif[bl]);
                float2 fo = unpack2(ago[bl]);
                redB4[(kc * 4 + bl) * 64 + u] = make_float4(fi.x, fi.y, fo.x, fo.y);
            }
        }
        __syncthreads();   // #3: redB stores + h2 read -> D

        // ---- D: layer 1 finalize (no trailing barrier; back-edge is free)
        {
            float4 pre = b1q;
#pragma unroll
            for (int kk = 0; kk < 4; kk++) {
                float4 q = redB4[(kk * 4 + kc) * 64 + u];
                pre.x += q.x; pre.y += q.y; pre.z += q.z; pre.w += q.w;
            }
            float h = final_gate(pre, c2);
            h2f[kc * 64 + u] = h;
        }
        // (h2 next read in C(t+1), after barriers #1,#2 of step t+1;
        //  redB next written in C(t+1), after #1,#2; redA read in B(t) is
        //  separated from A(t+1) write by #2,#3 — all pairs barrier-covered.)
    }
    __syncthreads();   // final h2 publish before classifier head

    // ---- classifier head: Linear(64,32) -> ReLU -> Linear(32,1) -> sigmoid
    if (tid < 128) {
        int cb = tid >> 5, m = tid & 31;
        float s = bfc1[m];
        const float* wr = Wfc1 + m * 64;
#pragma unroll
        for (int k = 0; k < 64; k++) s = fmaf(wr[k], h2f[cb * 64 + k], s);
        shid[cb * 32 + m] = fmaxf(s, 0.f);
    }
    __syncthreads();
    if (tid < NB) {
        float s = bfc2[0];
#pragma unroll
        for (int m = 0; m < 32; m++) s = fmaf(Wfc2[m], shid[tid * 32 + m], s);
        out[blockIdx.x * NB + tid] = sigm_f(s);
    }
}

extern "C" void kernel_launch(void* const* d_in, const int* in_sizes, int n_in,
                              void* d_out, int out_size) {
    const float* x    = (const float*)d_in[0];
    const float* Wih0 = (const float*)d_in[1];
    const float* Whh0 = (const float*)d_in[2];
    const float* b0   = (const float*)d_in[3];
    const float* Wih1 = (const float*)d_in[4];
    const float* Whh1 = (const float*)d_in[5];
    const float* b1   = (const float*)d_in[6];
    const float* Wfc1 = (const float*)d_in[7];
    const float* bfc1 = (const float*)d_in[8];
    const float* Wfc2 = (const float*)d_in[9];
    const float* bfc2 = (const float*)d_in[10];
    float* out = (float*)d_out;

    cudaFuncSetAttribute(lstm_persistent_kernel,
                         cudaFuncAttributeMaxDynamicSharedMemorySize, SMEM_BYTES);
    lstm_persistent_kernel<<<NBLK, NTHR, SMEM_BYTES>>>(
        x, Wih0, Whh0, b0, Wih1, Whh1, b1, Wfc1, bfc1, Wfc2, bfc2, out);
}